// round 1
// baseline (speedup 1.0000x reference)
#include <cuda_runtime.h>
#include <math.h>

#define LSEQ   2048
#define BATCH  4
#define NT     8192          // BATCH * LSEQ
#define CDIM   256
#define DIN    512
#define DSTATE 16
#define DTRANK 16

// ---------------- scratch (static __device__, no allocs) ----------------
__device__ float g_u [CDIM * NT];        //  8 MB  (C, B*L)  normalized input
__device__ float g_xz[2 * DIN * NT];     // 32 MB  (2*DIN, B*L) in_proj output
__device__ float g_xc[DIN * NT];         // 16 MB  (DIN, B*L) conv+silu output
__device__ float g_dt[NT * DTRANK];      // (B*L, 16)
__device__ float g_Bm[NT * DSTATE];      // (B*L, 16)
__device__ float g_Cm[NT * DSTATE];      // (B*L, 16)
__device__ float g_y [DIN * NT];         // 16 MB  (DIN, B*L) gated scan output
__device__ float g_op[CDIM * NT];        //  8 MB  (C, B*L) out_proj output

// ---------------- K1: input LayerNorm (over C), transpose to (C, B*L) ----
__global__ void ln_in_kernel(const float* __restrict__ x,
                             const float* __restrict__ w,
                             const float* __restrict__ bias) {
    int b  = blockIdx.y;
    int lx = threadIdx.x;                // l offset within 32-chunk
    int ty = threadIdx.y;                // c partition (8)
    int l  = blockIdx.x * 32 + lx;
    __shared__ float sS[8][32], sQ[8][32], sMean[32], sR[32];

    const float* xb = x + (size_t)b * CDIM * LSEQ + l;
    float s = 0.f, q = 0.f;
    for (int c = ty; c < CDIM; c += 8) {
        float v = xb[(size_t)c * LSEQ];
        s += v; q += v * v;
    }
    sS[ty][lx] = s; sQ[ty][lx] = q;
    __syncthreads();
    if (ty == 0) {
        float ts = 0.f, tq = 0.f;
        #pragma unroll
        for (int i = 0; i < 8; i++) { ts += sS[i][lx]; tq += sQ[i][lx]; }
        float m   = ts * (1.f / CDIM);
        float var = tq * (1.f / CDIM) - m * m;
        sMean[lx] = m;
        sR[lx]    = rsqrtf(var + 1e-5f);
    }
    __syncthreads();
    float m = sMean[lx], r = sR[lx];
    float* ub = g_u + (size_t)b * LSEQ + l;
    for (int c = ty; c < CDIM; c += 8) {
        float v = xb[(size_t)c * LSEQ];
        ub[(size_t)c * NT] = (v - m) * r * w[c] + bias[c];
    }
}

// ---------------- K2: generic fp32 tiled GEMM  C[M,N] = A[M,K] * B[K,N] ----
// M,N multiples of 64; K multiple of 16. 16x16 threads, 4x4 microtile.
__global__ void gemm64_kernel(const float* __restrict__ A,
                              const float* __restrict__ Bp,
                              float* __restrict__ Cp,
                              int M, int N, int K) {
    __shared__ float As[64][16];
    __shared__ float Bs[16][64];
    int tx = threadIdx.x, ty = threadIdx.y;
    int tid = ty * 16 + tx;
    int m0 = blockIdx.y * 64, n0 = blockIdx.x * 64;

    float acc[4][4];
    #pragma unroll
    for (int i = 0; i < 4; i++)
        #pragma unroll
        for (int j = 0; j < 4; j++) acc[i][j] = 0.f;

    int arow = tid >> 2,  acol = (tid & 3) * 4;    // A tile 64x16
    int brow = tid >> 4,  bcol = (tid & 15) * 4;   // B tile 16x64

    for (int k0 = 0; k0 < K; k0 += 16) {
        float4 av = *(const float4*)(A + (size_t)(m0 + arow) * K + k0 + acol);
        As[arow][acol + 0] = av.x;
        As[arow][acol + 1] = av.y;
        As[arow][acol + 2] = av.z;
        As[arow][acol + 3] = av.w;
        float4 bv = *(const float4*)(Bp + (size_t)(k0 + brow) * N + n0 + bcol);
        *(float4*)&Bs[brow][bcol] = bv;
        __syncthreads();
        #pragma unroll
        for (int k = 0; k < 16; k++) {
            float a0 = As[ty * 4 + 0][k];
            float a1 = As[ty * 4 + 1][k];
            float a2 = As[ty * 4 + 2][k];
            float a3 = As[ty * 4 + 3][k];
            float4 b4 = *(float4*)&Bs[k][tx * 4];
            acc[0][0] = fmaf(a0, b4.x, acc[0][0]); acc[0][1] = fmaf(a0, b4.y, acc[0][1]);
            acc[0][2] = fmaf(a0, b4.z, acc[0][2]); acc[0][3] = fmaf(a0, b4.w, acc[0][3]);
            acc[1][0] = fmaf(a1, b4.x, acc[1][0]); acc[1][1] = fmaf(a1, b4.y, acc[1][1]);
            acc[1][2] = fmaf(a1, b4.z, acc[1][2]); acc[1][3] = fmaf(a1, b4.w, acc[1][3]);
            acc[2][0] = fmaf(a2, b4.x, acc[2][0]); acc[2][1] = fmaf(a2, b4.y, acc[2][1]);
            acc[2][2] = fmaf(a2, b4.z, acc[2][2]); acc[2][3] = fmaf(a2, b4.w, acc[2][3]);
            acc[3][0] = fmaf(a3, b4.x, acc[3][0]); acc[3][1] = fmaf(a3, b4.y, acc[3][1]);
            acc[3][2] = fmaf(a3, b4.z, acc[3][2]); acc[3][3] = fmaf(a3, b4.w, acc[3][3]);
        }
        __syncthreads();
    }
    #pragma unroll
    for (int i = 0; i < 4; i++) {
        float4 o = make_float4(acc[i][0], acc[i][1], acc[i][2], acc[i][3]);
        *(float4*)(Cp + (size_t)(m0 + ty * 4 + i) * N + n0 + tx * 4) = o;
    }
}

// ---------------- K3: causal depthwise conv (width 4) + SiLU ----------------
__global__ void conv_kernel(const float* __restrict__ cw,
                            const float* __restrict__ cb) {
    int d = blockIdx.y;
    int n = blockIdx.x * 256 + threadIdx.x;
    const float* xin = g_xz + (size_t)d * NT;
    float w0 = cw[d * 4 + 0], w1 = cw[d * 4 + 1];
    float w2 = cw[d * 4 + 2], w3 = cw[d * 4 + 3];
    int l = n & (LSEQ - 1);
    float v = cb[d] + w3 * xin[n];
    if (l >= 1) v = fmaf(w2, xin[n - 1], v);
    if (l >= 2) v = fmaf(w1, xin[n - 2], v);
    if (l >= 3) v = fmaf(w0, xin[n - 3], v);
    v = v / (1.f + __expf(-v));          // SiLU
    g_xc[(size_t)d * NT + n] = v;
}

// ---------------- K4: x_proj (48x512) @ xc -> dt/Bm/Cm in (n,16) layout -----
__global__ void xproj_kernel(const float* __restrict__ W) {
    __shared__ float sW[48 * 128];
    int lx = threadIdx.x;        // 32 (n offset)
    int ty = threadIdx.y;        // 16 (k group of 3)
    int n  = blockIdx.x * 32 + lx;
    int tid = ty * 32 + lx;      // 0..511
    float a0 = 0.f, a1 = 0.f, a2 = 0.f;
    int k0 = ty * 3;
    for (int d0 = 0; d0 < DIN; d0 += 128) {
        __syncthreads();
        for (int i = tid; i < 48 * 128; i += 512) {
            int k = i >> 7, dd = i & 127;
            sW[i] = W[(size_t)k * DIN + d0 + dd];
        }
        __syncthreads();
        for (int dd = 0; dd < 128; dd++) {
            float xv = g_xc[(size_t)(d0 + dd) * NT + n];
            a0 = fmaf(xv, sW[(k0 + 0) * 128 + dd], a0);
            a1 = fmaf(xv, sW[(k0 + 1) * 128 + dd], a1);
            a2 = fmaf(xv, sW[(k0 + 2) * 128 + dd], a2);
        }
    }
    float accs[3] = {a0, a1, a2};
    #pragma unroll
    for (int i = 0; i < 3; i++) {
        int k = k0 + i;
        if (k < DTRANK)                    g_dt[(size_t)n * 16 + k] = accs[i];
        else if (k < DTRANK + DSTATE)      g_Bm[(size_t)n * 16 + (k - DTRANK)] = accs[i];
        else                               g_Cm[(size_t)n * 16 + (k - DTRANK - DSTATE)] = accs[i];
    }
}

// ---------------- K5: fused dt_proj + softplus + selective scan + gating ----
// 16 lanes per (b,d); block = 256 threads = 16 d-channels.
__global__ void scan_kernel(const float* __restrict__ dtw,
                            const float* __restrict__ dtb,
                            const float* __restrict__ Alog,
                            const float* __restrict__ Dp) {
    int b = blockIdx.y;
    int g = threadIdx.x >> 4;
    int nl = threadIdx.x & 15;
    int d = blockIdx.x * 16 + g;

    float Adn = -__expf(Alog[d * DSTATE + nl]);
    float wdt = dtw[d * DTRANK + nl];
    float bdt = dtb[d];
    float Dd  = Dp[d];
    float h = 0.f;

    const float* xcrow = g_xc + (size_t)d * NT + (size_t)b * LSEQ;
    const float* zrow  = g_xz + (size_t)(DIN + d) * NT + (size_t)b * LSEQ;
    float*       yrow  = g_y  + (size_t)d * NT + (size_t)b * LSEQ;
    const float* dtp = g_dt + (size_t)b * LSEQ * 16;
    const float* Bp  = g_Bm + (size_t)b * LSEQ * 16;
    const float* Cp  = g_Cm + (size_t)b * LSEQ * 16;

    #pragma unroll 4
    for (int l = 0; l < LSEQ; l++) {
        float s = dtp[l * 16 + nl] * wdt;
        s += __shfl_xor_sync(0xffffffffu, s, 1);
        s += __shfl_xor_sync(0xffffffffu, s, 2);
        s += __shfl_xor_sync(0xffffffffu, s, 4);
        s += __shfl_xor_sync(0xffffffffu, s, 8);
        s += bdt;
        float delta = (s > 20.f) ? s : log1pf(__expf(s));
        float xcv = xcrow[l];
        float Bv = Bp[l * 16 + nl];
        float Cv = Cp[l * 16 + nl];
        float dA = __expf(delta * Adn);
        h = fmaf(dA, h, delta * Bv * xcv);
        float yv = h * Cv;
        yv += __shfl_xor_sync(0xffffffffu, yv, 1);
        yv += __shfl_xor_sync(0xffffffffu, yv, 2);
        yv += __shfl_xor_sync(0xffffffffu, yv, 4);
        yv += __shfl_xor_sync(0xffffffffu, yv, 8);
        if (nl == 0) {
            float zl = zrow[l];
            float silu = zl / (1.f + __expf(-zl));
            yrow[l] = (yv + Dd * xcv) * silu;
        }
    }
}

// ---------------- K6: residual + output LayerNorm, write (B,C,L,1) ---------
__global__ void ln_out_kernel(const float* __restrict__ x,
                              const float* __restrict__ w,
                              const float* __restrict__ bias,
                              float* __restrict__ out) {
    int b  = blockIdx.y;
    int lx = threadIdx.x;
    int ty = threadIdx.y;
    int l  = blockIdx.x * 32 + lx;
    __shared__ float sS[8][32], sQ[8][32], sMean[32], sR[32];

    const float* xb = x + (size_t)b * CDIM * LSEQ + l;
    const float* ob = g_op + (size_t)b * LSEQ + l;
    float s = 0.f, q = 0.f;
    for (int c = ty; c < CDIM; c += 8) {
        float v = ob[(size_t)c * NT] + xb[(size_t)c * LSEQ];
        s += v; q += v * v;
    }
    sS[ty][lx] = s; sQ[ty][lx] = q;
    __syncthreads();
    if (ty == 0) {
        float ts = 0.f, tq = 0.f;
        #pragma unroll
        for (int i = 0; i < 8; i++) { ts += sS[i][lx]; tq += sQ[i][lx]; }
        float m   = ts * (1.f / CDIM);
        float var = tq * (1.f / CDIM) - m * m;
        sMean[lx] = m;
        sR[lx]    = rsqrtf(var + 1e-5f);
    }
    __syncthreads();
    float m = sMean[lx], r = sR[lx];
    float* outb = out + (size_t)b * CDIM * LSEQ + l;
    for (int c = ty; c < CDIM; c += 8) {
        float v = ob[(size_t)c * NT] + xb[(size_t)c * LSEQ];
        outb[(size_t)c * LSEQ] = (v - m) * r * w[c] + bias[c];
    }
}

// ---------------- launch -----------------------------------------------------
extern "C" void kernel_launch(void* const* d_in, const int* in_sizes, int n_in,
                              void* d_out, int out_size) {
    const float* x         = (const float*)d_in[0];
    const float* ln_w      = (const float*)d_in[1];
    const float* ln_b      = (const float*)d_in[2];
    const float* in_proj_w = (const float*)d_in[3];
    const float* conv_w    = (const float*)d_in[4];
    const float* conv_b    = (const float*)d_in[5];
    const float* x_proj_w  = (const float*)d_in[6];
    const float* dt_proj_w = (const float*)d_in[7];
    const float* dt_proj_b = (const float*)d_in[8];
    const float* A_log     = (const float*)d_in[9];
    const float* Dv        = (const float*)d_in[10];
    const float* out_proj_w= (const float*)d_in[11];
    float* out = (float*)d_out;

    float *p_u, *p_xz, *p_xc, *p_y, *p_op;
    cudaGetSymbolAddress((void**)&p_u,  g_u);
    cudaGetSymbolAddress((void**)&p_xz, g_xz);
    cudaGetSymbolAddress((void**)&p_xc, g_xc);
    cudaGetSymbolAddress((void**)&p_y,  g_y);
    cudaGetSymbolAddress((void**)&p_op, g_op);

    dim3 lnBlock(32, 8);
    dim3 lnGrid(LSEQ / 32, BATCH);
    ln_in_kernel<<<lnGrid, lnBlock>>>(x, ln_w, ln_b);

    // in_proj: (1024 x 256) @ (256 x 8192)
    gemm64_kernel<<<dim3(NT / 64, (2 * DIN) / 64), dim3(16, 16)>>>(
        in_proj_w, p_u, p_xz, 2 * DIN, NT, CDIM);

    conv_kernel<<<dim3(NT / 256, DIN), 256>>>(conv_w, conv_b);

    xproj_kernel<<<dim3(NT / 32), dim3(32, 16)>>>(x_proj_w);

    scan_kernel<<<dim3(DIN / 16, BATCH), 256>>>(dt_proj_w, dt_proj_b, A_log, Dv);

    // out_proj: (256 x 512) @ (512 x 8192)
    gemm64_kernel<<<dim3(NT / 64, CDIM / 64), dim3(16, 16)>>>(
        out_proj_w, p_y, p_op, CDIM, NT, DIN);

    ln_out_kernel<<<lnGrid, lnBlock>>>(x, ln_w, ln_b, out);
}

// round 2
// speedup vs baseline: 1.2813x; 1.2813x over previous
#include <cuda_runtime.h>
#include <math.h>

#define LSEQ   2048
#define BATCH  4
#define NT     8192          // BATCH * LSEQ
#define CDIM   256
#define DIN    512
#define DSTATE 16
#define DTRANK 16

// ---------------- scratch (static __device__, no allocs) ----------------
__device__ float g_u    [CDIM * NT];        //  8 MB  (C, B*L)  normalized input
__device__ float g_xz   [2 * DIN * NT];     // 32 MB  (2*DIN, B*L) in_proj output
__device__ float g_xc   [DIN * NT];         // 16 MB  (DIN, B*L) conv+silu output
__device__ float g_dt   [NT * DTRANK];      // (B*L, 16)
__device__ float g_Bm   [NT * DSTATE];      // (B*L, 16)
__device__ float g_Cm   [NT * DSTATE];      // (B*L, 16)
__device__ float g_delta[DIN * NT];         // 16 MB  (DIN, B*L) softplus(dt_proj)
__device__ float g_y    [DIN * NT];         // 16 MB  (DIN, B*L) gated scan output
__device__ float g_op   [CDIM * NT];        //  8 MB  (C, B*L) out_proj output

// ---------------- K1: input LayerNorm (over C), transpose to (C, B*L) ----
__global__ void ln_in_kernel(const float* __restrict__ x,
                             const float* __restrict__ w,
                             const float* __restrict__ bias) {
    int b  = blockIdx.y;
    int lx = threadIdx.x;                // l offset within 32-chunk
    int ty = threadIdx.y;                // c partition (8)
    int l  = blockIdx.x * 32 + lx;
    __shared__ float sS[8][32], sQ[8][32], sMean[32], sR[32];

    const float* xb = x + (size_t)b * CDIM * LSEQ + l;
    float s = 0.f, q = 0.f;
    for (int c = ty; c < CDIM; c += 8) {
        float v = xb[(size_t)c * LSEQ];
        s += v; q += v * v;
    }
    sS[ty][lx] = s; sQ[ty][lx] = q;
    __syncthreads();
    if (ty == 0) {
        float ts = 0.f, tq = 0.f;
        #pragma unroll
        for (int i = 0; i < 8; i++) { ts += sS[i][lx]; tq += sQ[i][lx]; }
        float m   = ts * (1.f / CDIM);
        float var = tq * (1.f / CDIM) - m * m;
        sMean[lx] = m;
        sR[lx]    = rsqrtf(var + 1e-5f);
    }
    __syncthreads();
    float m = sMean[lx], r = sR[lx];
    float* ub = g_u + (size_t)b * LSEQ + l;
    for (int c = ty; c < CDIM; c += 8) {
        float v = xb[(size_t)c * LSEQ];
        ub[(size_t)c * NT] = (v - m) * r * w[c] + bias[c];
    }
}

// ---------------- K2: fp32 GEMM, 128x128 tile, 8x8 micro, double-buffered ----
// C[M,N] = A[M,K] * B[K,N].  M % 128 == 0, N % 128 == 0, K % 16 == 0.
// Bs columns get a 4-float pad every 32 cols so the 8-lane B-frag float4
// reads land in 8 distinct banks (no 2-way 128B-apart conflicts).
#define BPAD(c) ((c) + (((c) >> 5) << 2))
__global__ __launch_bounds__(256, 2)
void gemm128_kernel(const float* __restrict__ A, const float* __restrict__ B,
                    float* __restrict__ C, int M, int N, int K) {
    __shared__ float As[2][16][132];
    __shared__ float Bs[2][16][144];
    const int tid = threadIdx.x;
    const int m0 = blockIdx.y * 128, n0 = blockIdx.x * 128;

    const int arow = tid >> 2;            // 0..63
    const int acol = (tid & 3) << 2;      // 0/4/8/12
    const int brow = tid >> 5;            // 0..7
    const int bcol = (tid & 31) << 2;     // 0..124
    const int bcs  = BPAD(bcol);

    const float* Ap = A + (size_t)(m0 + arow) * K + acol;
    const float* Bp = B + (size_t)brow * N + n0 + bcol;

    const int lane = tid & 31, wid = tid >> 5;
    const int wm = (wid & 3) * 32, wn = (wid >> 2) * 64;
    const int cm = wm + ((lane & 3) << 3);       // acc row base (8 rows)
    const int cn = wn + ((lane >> 2) << 3);      // acc col base (8 cols)
    const int cns = BPAD(cn);

    float acc[8][8];
    #pragma unroll
    for (int i = 0; i < 8; i++)
        #pragma unroll
        for (int j = 0; j < 8; j++) acc[i][j] = 0.f;

    // ---- load tile 0 ----
    {
        float4 a0 = *(const float4*)(Ap);
        float4 a1 = *(const float4*)(Ap + (size_t)64 * K);
        float4 b0 = *(const float4*)(Bp);
        float4 b1 = *(const float4*)(Bp + (size_t)8 * N);
        As[0][acol + 0][arow] = a0.x;  As[0][acol + 1][arow] = a0.y;
        As[0][acol + 2][arow] = a0.z;  As[0][acol + 3][arow] = a0.w;
        As[0][acol + 0][arow + 64] = a1.x;  As[0][acol + 1][arow + 64] = a1.y;
        As[0][acol + 2][arow + 64] = a1.z;  As[0][acol + 3][arow + 64] = a1.w;
        *(float4*)&Bs[0][brow][bcs]     = b0;
        *(float4*)&Bs[0][brow + 8][bcs] = b1;
    }
    __syncthreads();

    const int nk = K >> 4;
    for (int kt = 0; kt < nk; kt++) {
        const int buf = kt & 1;
        float4 na0, na1, nb0, nb1;
        const bool more = (kt + 1 < nk);
        if (more) {
            const float* Ap2 = Ap + (kt + 1) * 16;
            na0 = *(const float4*)(Ap2);
            na1 = *(const float4*)(Ap2 + (size_t)64 * K);
            const float* Bp2 = Bp + (size_t)(kt + 1) * 16 * N;
            nb0 = *(const float4*)(Bp2);
            nb1 = *(const float4*)(Bp2 + (size_t)8 * N);
        }
        #pragma unroll
        for (int k = 0; k < 16; k++) {
            float ar[8], br[8];
            *(float4*)(ar)     = *(float4*)&As[buf][k][cm];
            *(float4*)(ar + 4) = *(float4*)&As[buf][k][cm + 4];
            *(float4*)(br)     = *(float4*)&Bs[buf][k][cns];
            *(float4*)(br + 4) = *(float4*)&Bs[buf][k][cns + 4];
            #pragma unroll
            for (int i = 0; i < 8; i++)
                #pragma unroll
                for (int j = 0; j < 8; j++)
                    acc[i][j] = fmaf(ar[i], br[j], acc[i][j]);
        }
        if (more) {
            const int nb = buf ^ 1;
            As[nb][acol + 0][arow] = na0.x;  As[nb][acol + 1][arow] = na0.y;
            As[nb][acol + 2][arow] = na0.z;  As[nb][acol + 3][arow] = na0.w;
            As[nb][acol + 0][arow + 64] = na1.x;  As[nb][acol + 1][arow + 64] = na1.y;
            As[nb][acol + 2][arow + 64] = na1.z;  As[nb][acol + 3][arow + 64] = na1.w;
            *(float4*)&Bs[nb][brow][bcs]     = nb0;
            *(float4*)&Bs[nb][brow + 8][bcs] = nb1;
            __syncthreads();
        }
    }

    #pragma unroll
    for (int i = 0; i < 8; i++) {
        float* crow = C + (size_t)(m0 + cm + i) * N + n0 + cn;
        *(float4*)(crow)     = make_float4(acc[i][0], acc[i][1], acc[i][2], acc[i][3]);
        *(float4*)(crow + 4) = make_float4(acc[i][4], acc[i][5], acc[i][6], acc[i][7]);
    }
}

// ---------------- K3: causal depthwise conv (width 4) + SiLU ----------------
__global__ void conv_kernel(const float* __restrict__ cw,
                            const float* __restrict__ cb) {
    int d = blockIdx.y;
    int n = blockIdx.x * 256 + threadIdx.x;
    const float* xin = g_xz + (size_t)d * NT;
    float w0 = cw[d * 4 + 0], w1 = cw[d * 4 + 1];
    float w2 = cw[d * 4 + 2], w3 = cw[d * 4 + 3];
    int l = n & (LSEQ - 1);
    float v = cb[d] + w3 * xin[n];
    if (l >= 1) v = fmaf(w2, xin[n - 1], v);
    if (l >= 2) v = fmaf(w1, xin[n - 2], v);
    if (l >= 3) v = fmaf(w0, xin[n - 3], v);
    v = v / (1.f + __expf(-v));          // SiLU
    g_xc[(size_t)d * NT + n] = v;
}

// ---------------- K4: x_proj (48x512) @ xc -> dt/Bm/Cm in (n,16) layout -----
// Block: 256 threads handles 64 n-columns; K streamed in 64-chunks via smem.
__global__ void xproj_kernel(const float* __restrict__ W) {
    __shared__ float Ws[48][64];
    __shared__ float Xs[64][68];
    int t  = threadIdx.x;
    int n0 = blockIdx.x * 64;
    int tn = t & 63, tk = t >> 6;        // tk 0..3, each owns 12 k-rows
    float acc[12];
    #pragma unroll
    for (int j = 0; j < 12; j++) acc[j] = 0.f;

    for (int d0 = 0; d0 < DIN; d0 += 64) {
        __syncthreads();
        for (int i = t; i < 768; i += 256) {           // W chunk 48x64
            int r = i >> 4, c4 = (i & 15) << 2;
            *(float4*)&Ws[r][c4] = *(const float4*)&W[(size_t)r * DIN + d0 + c4];
        }
        for (int i = t; i < 1024; i += 256) {          // X chunk 64x64
            int r = i >> 4, c4 = (i & 15) << 2;
            *(float4*)&Xs[r][c4] = *(const float4*)&g_xc[(size_t)(d0 + r) * NT + n0 + c4];
        }
        __syncthreads();
        #pragma unroll 4
        for (int dd = 0; dd < 64; dd++) {
            float xv = Xs[dd][tn];
            #pragma unroll
            for (int j = 0; j < 12; j++)
                acc[j] = fmaf(xv, Ws[tk * 12 + j][dd], acc[j]);
        }
    }
    int n = n0 + tn;
    #pragma unroll
    for (int j = 0; j < 12; j++) {
        int k = tk * 12 + j;
        if (k < DTRANK)                g_dt[(size_t)n * 16 + k] = acc[j];
        else if (k < DTRANK + DSTATE)  g_Bm[(size_t)n * 16 + (k - DTRANK)] = acc[j];
        else                           g_Cm[(size_t)n * 16 + (k - DTRANK - DSTATE)] = acc[j];
    }
}

// ---------------- K5: delta = softplus(dt @ dtw^T + dtb)  -> (DIN, NT) ------
__global__ void delta_kernel(const float* __restrict__ dtw,
                             const float* __restrict__ dtb) {
    int d = blockIdx.y;
    int n = blockIdx.x * 256 + threadIdx.x;
    float s = dtb[d];
    const float4* dtn = (const float4*)(g_dt + (size_t)n * 16);
    const float4* wr  = (const float4*)(dtw + d * 16);
    #pragma unroll
    for (int q = 0; q < 4; q++) {
        float4 a = dtn[q], b = wr[q];
        s += a.x * b.x + a.y * b.y + a.z * b.z + a.w * b.w;
    }
    float delta = (s > 20.f) ? s : log1pf(__expf(s));
    g_delta[(size_t)d * NT + n] = delta;
}

// ---------------- K6: selective scan + D skip + SiLU(z) gating --------------
// 16 lanes per (b,d); block = 256 threads = 16 d-channels.
__global__ void scan_kernel(const float* __restrict__ Alog,
                            const float* __restrict__ Dp) {
    int b = blockIdx.y;
    int g = threadIdx.x >> 4;
    int nl = threadIdx.x & 15;
    int d = blockIdx.x * 16 + g;

    float Adn = -__expf(Alog[d * DSTATE + nl]);
    float Dd  = Dp[d];
    float h = 0.f;

    const float* drow  = g_delta + (size_t)d * NT + (size_t)b * LSEQ;
    const float* xcrow = g_xc + (size_t)d * NT + (size_t)b * LSEQ;
    const float* zrow  = g_xz + (size_t)(DIN + d) * NT + (size_t)b * LSEQ;
    float*       yrow  = g_y  + (size_t)d * NT + (size_t)b * LSEQ;
    const float* Bp  = g_Bm + (size_t)b * LSEQ * 16;
    const float* Cp  = g_Cm + (size_t)b * LSEQ * 16;

    #pragma unroll 4
    for (int l = 0; l < LSEQ; l++) {
        float delta = drow[l];
        float xcv = xcrow[l];
        float Bv = Bp[l * 16 + nl];
        float Cv = Cp[l * 16 + nl];
        float dA = __expf(delta * Adn);
        h = fmaf(dA, h, delta * Bv * xcv);
        float yv = h * Cv;
        yv += __shfl_xor_sync(0xffffffffu, yv, 1);
        yv += __shfl_xor_sync(0xffffffffu, yv, 2);
        yv += __shfl_xor_sync(0xffffffffu, yv, 4);
        yv += __shfl_xor_sync(0xffffffffu, yv, 8);
        if (nl == 0) {
            float zl = zrow[l];
            float silu = zl / (1.f + __expf(-zl));
            yrow[l] = (yv + Dd * xcv) * silu;
        }
    }
}

// ---------------- K7: residual + output LayerNorm, write (B,C,L,1) ---------
__global__ void ln_out_kernel(const float* __restrict__ x,
                              const float* __restrict__ w,
                              const float* __restrict__ bias,
                              float* __restrict__ out) {
    int b  = blockIdx.y;
    int lx = threadIdx.x;
    int ty = threadIdx.y;
    int l  = blockIdx.x * 32 + lx;
    __shared__ float sS[8][32], sQ[8][32], sMean[32], sR[32];

    const float* xb = x + (size_t)b * CDIM * LSEQ + l;
    const float* ob = g_op + (size_t)b * LSEQ + l;
    float s = 0.f, q = 0.f;
    for (int c = ty; c < CDIM; c += 8) {
        float v = ob[(size_t)c * NT] + xb[(size_t)c * LSEQ];
        s += v; q += v * v;
    }
    sS[ty][lx] = s; sQ[ty][lx] = q;
    __syncthreads();
    if (ty == 0) {
        float ts = 0.f, tq = 0.f;
        #pragma unroll
        for (int i = 0; i < 8; i++) { ts += sS[i][lx]; tq += sQ[i][lx]; }
        float m   = ts * (1.f / CDIM);
        float var = tq * (1.f / CDIM) - m * m;
        sMean[lx] = m;
        sR[lx]    = rsqrtf(var + 1e-5f);
    }
    __syncthreads();
    float m = sMean[lx], r = sR[lx];
    float* outb = out + (size_t)b * CDIM * LSEQ + l;
    for (int c = ty; c < CDIM; c += 8) {
        float v = ob[(size_t)c * NT] + xb[(size_t)c * LSEQ];
        outb[(size_t)c * LSEQ] = (v - m) * r * w[c] + bias[c];
    }
}

// ---------------- launch -----------------------------------------------------
extern "C" void kernel_launch(void* const* d_in, const int* in_sizes, int n_in,
                              void* d_out, int out_size) {
    const float* x         = (const float*)d_in[0];
    const float* ln_w      = (const float*)d_in[1];
    const float* ln_b      = (const float*)d_in[2];
    const float* in_proj_w = (const float*)d_in[3];
    const float* conv_w    = (const float*)d_in[4];
    const float* conv_b    = (const float*)d_in[5];
    const float* x_proj_w  = (const float*)d_in[6];
    const float* dt_proj_w = (const float*)d_in[7];
    const float* dt_proj_b = (const float*)d_in[8];
    const float* A_log     = (const float*)d_in[9];
    const float* Dv        = (const float*)d_in[10];
    const float* out_proj_w= (const float*)d_in[11];
    float* out = (float*)d_out;

    float *p_u, *p_xz, *p_y, *p_op;
    cudaGetSymbolAddress((void**)&p_u,  g_u);
    cudaGetSymbolAddress((void**)&p_xz, g_xz);
    cudaGetSymbolAddress((void**)&p_y,  g_y);
    cudaGetSymbolAddress((void**)&p_op, g_op);

    dim3 lnBlock(32, 8);
    dim3 lnGrid(LSEQ / 32, BATCH);
    ln_in_kernel<<<lnGrid, lnBlock>>>(x, ln_w, ln_b);

    // in_proj: (1024 x 256) @ (256 x 8192)
    gemm128_kernel<<<dim3(NT / 128, (2 * DIN) / 128), 256>>>(
        in_proj_w, p_u, p_xz, 2 * DIN, NT, CDIM);

    conv_kernel<<<dim3(NT / 256, DIN), 256>>>(conv_w, conv_b);

    xproj_kernel<<<dim3(NT / 64), 256>>>(x_proj_w);

    delta_kernel<<<dim3(NT / 256, DIN), 256>>>(dt_proj_w, dt_proj_b);

    scan_kernel<<<dim3(DIN / 16, BATCH), 256>>>(A_log, Dv);

    // out_proj: (256 x 512) @ (512 x 8192)
    gemm128_kernel<<<dim3(NT / 128, CDIM / 128), 256>>>(
        out_proj_w, p_y, p_op, CDIM, NT, DIN);

    ln_out_kernel<<<lnGrid, lnBlock>>>(x, ln_w, ln_b, out);
}

// round 3
// speedup vs baseline: 3.4779x; 2.7143x over previous
#include <cuda_runtime.h>
#include <cuda_bf16.h>
#include <math.h>
#include <stdint.h>

#define LSEQ   2048
#define BATCH  4
#define NT     8192          // BATCH * LSEQ
#define CDIM   256
#define DIN    512
#define DSTATE 16
#define DTRANK 16
#define NCHUNK 32
#define CHLEN  64            // LSEQ / NCHUNK

// ---------------- scratch (static __device__, no allocs) ----------------
__device__ float g_u    [NT * CDIM];        //  8 MB  (B*L, C)   n-major normalized input
__device__ float g_xz   [2 * DIN * NT];     // 32 MB  (2*DIN, B*L) in_proj output (m-major)
__device__ float g_xc   [DIN * NT];         // 16 MB  (DIN, B*L) conv+silu output
__device__ float g_dt   [NT * DTRANK];      // (B*L, 16)
__device__ float g_Bm   [NT * DSTATE];      // (B*L, 16)
__device__ float g_Cm   [NT * DSTATE];      // (B*L, 16)
__device__ float g_delta[DIN * NT];         // 16 MB  (DIN, B*L) softplus(dt_proj)
__device__ float g_y    [NT * DIN];         // 16 MB  (B*L, DIN) n-major gated scan output
__device__ float g_op   [CDIM * NT];        //  8 MB  (C, B*L) out_proj output
__device__ float g_P    [BATCH * NCHUNK * DIN * DSTATE];   // 4 MB chunk products
__device__ float g_q    [BATCH * NCHUNK * DIN * DSTATE];   // 4 MB chunk offsets
__device__ float g_h0   [BATCH * NCHUNK * DIN * DSTATE];   // 4 MB chunk-start states

__device__ __forceinline__ uint32_t s2u(const void* p) {
    return (uint32_t)__cvta_generic_to_shared(p);
}
__device__ __forceinline__ void ldsm4(uint32_t* r, uint32_t addr) {
    asm volatile("ldmatrix.sync.aligned.m8n8.x4.shared.b16 {%0,%1,%2,%3}, [%4];"
        : "=r"(r[0]), "=r"(r[1]), "=r"(r[2]), "=r"(r[3]) : "r"(addr));
}
__device__ __forceinline__ void mma16816(float* c, const uint32_t* a, uint32_t b0, uint32_t b1) {
    asm volatile("mma.sync.aligned.m16n8k16.row.col.f32.bf16.bf16.f32 "
        "{%0,%1,%2,%3}, {%4,%5,%6,%7}, {%8,%9}, {%0,%1,%2,%3};"
        : "+f"(c[0]), "+f"(c[1]), "+f"(c[2]), "+f"(c[3])
        : "r"(a[0]), "r"(a[1]), "r"(a[2]), "r"(a[3]), "r"(b0), "r"(b1));
}

// ---------------- K1: input LayerNorm (over C), output n-major (NT, C) ----
__global__ void ln_in_kernel(const float* __restrict__ x,
                             const float* __restrict__ w,
                             const float* __restrict__ bias) {
    int b  = blockIdx.y;
    int tid = threadIdx.x;
    int lx = tid & 31;            // l offset within 32-chunk
    int ty = tid >> 5;            // c partition (8)
    int l0 = blockIdx.x * 32;
    __shared__ float T[CDIM][33];
    __shared__ float sS[8][32], sQ[8][32], sMean[32], sR[32];

    const float* xb = x + (size_t)b * CDIM * LSEQ + l0 + lx;
    float s = 0.f, q = 0.f;
    for (int c = ty; c < CDIM; c += 8) {
        float v = xb[(size_t)c * LSEQ];
        T[c][lx] = v;
        s += v; q += v * v;
    }
    sS[ty][lx] = s; sQ[ty][lx] = q;
    __syncthreads();
    if (ty == 0) {
        float ts = 0.f, tq = 0.f;
        #pragma unroll
        for (int i = 0; i < 8; i++) { ts += sS[i][lx]; tq += sQ[i][lx]; }
        float m   = ts * (1.f / CDIM);
        float var = tq * (1.f / CDIM) - m * m;
        sMean[lx] = m;
        sR[lx]    = rsqrtf(var + 1e-5f);
    }
    __syncthreads();
    int c = tid;                      // 0..255
    float wc = w[c], bc = bias[c];
    #pragma unroll 4
    for (int l = 0; l < 32; l++) {
        float v = T[c][l];
        g_u[(size_t)(b * LSEQ + l0 + l) * CDIM + c] = (v - sMean[l]) * sR[l] * wc + bc;
    }
}

// ---------------- K2: tensor-core TN GEMM with bf16 hi/lo split -------------
// C[M,N] = A[M,K] * Bn[N,K]^T.  A row-major (M,K), Bn row-major (N,K).
// BM=128 BN=64 BK=32; 8 warps as 4(m) x 2(n); warp tile 32x32.
__global__ __launch_bounds__(256, 2)
void gemm_tc_kernel(const float* __restrict__ A, const float* __restrict__ Bn,
                    float* __restrict__ C, int M, int N, int K) {
    __shared__ __nv_bfloat16 Ah[128][40], Al[128][40], Bh[64][40], Bl[64][40];
    const int tid = threadIdx.x, lane = tid & 31, wid = tid >> 5;
    const int m0 = blockIdx.y * 128, n0 = blockIdx.x * 64;
    const int wm = (wid & 3) * 32;
    const int wn = (wid >> 2) * 32;
    const int lr = lane & 15;
    const int lc = (lane & 16) ? 8 : 0;

    float acc[2][4][4];
    #pragma unroll
    for (int mi = 0; mi < 2; mi++)
        #pragma unroll
        for (int nf = 0; nf < 4; nf++)
            #pragma unroll
            for (int e = 0; e < 4; e++) acc[mi][nf][e] = 0.f;

    const int grow = tid >> 3;           // 0..31
    const int gcol = (tid & 7) << 2;     // 0..28

    for (int k0 = 0; k0 < K; k0 += 32) {
        // ---- load + convert A tile (128 x 32) ----
        #pragma unroll
        for (int i = 0; i < 4; i++) {
            int r = grow + 32 * i;
            float4 v = *(const float4*)&A[(size_t)(m0 + r) * K + k0 + gcol];
            __nv_bfloat16 h0 = __float2bfloat16(v.x);
            __nv_bfloat16 h1 = __float2bfloat16(v.y);
            __nv_bfloat16 h2 = __float2bfloat16(v.z);
            __nv_bfloat16 h3 = __float2bfloat16(v.w);
            __nv_bfloat162 hh0; hh0.x = h0; hh0.y = h1;
            __nv_bfloat162 hh1; hh1.x = h2; hh1.y = h3;
            *(__nv_bfloat162*)&Ah[r][gcol]     = hh0;
            *(__nv_bfloat162*)&Ah[r][gcol + 2] = hh1;
            __nv_bfloat162 ll0, ll1;
            ll0.x = __float2bfloat16(v.x - __bfloat162float(h0));
            ll0.y = __float2bfloat16(v.y - __bfloat162float(h1));
            ll1.x = __float2bfloat16(v.z - __bfloat162float(h2));
            ll1.y = __float2bfloat16(v.w - __bfloat162float(h3));
            *(__nv_bfloat162*)&Al[r][gcol]     = ll0;
            *(__nv_bfloat162*)&Al[r][gcol + 2] = ll1;
        }
        // ---- load + convert B tile (64 x 32) ----
        #pragma unroll
        for (int i = 0; i < 2; i++) {
            int r = grow + 32 * i;
            float4 v = *(const float4*)&Bn[(size_t)(n0 + r) * K + k0 + gcol];
            __nv_bfloat16 h0 = __float2bfloat16(v.x);
            __nv_bfloat16 h1 = __float2bfloat16(v.y);
            __nv_bfloat16 h2 = __float2bfloat16(v.z);
            __nv_bfloat16 h3 = __float2bfloat16(v.w);
            __nv_bfloat162 hh0; hh0.x = h0; hh0.y = h1;
            __nv_bfloat162 hh1; hh1.x = h2; hh1.y = h3;
            *(__nv_bfloat162*)&Bh[r][gcol]     = hh0;
            *(__nv_bfloat162*)&Bh[r][gcol + 2] = hh1;
            __nv_bfloat162 ll0, ll1;
            ll0.x = __float2bfloat16(v.x - __bfloat162float(h0));
            ll0.y = __float2bfloat16(v.y - __bfloat162float(h1));
            ll1.x = __float2bfloat16(v.z - __bfloat162float(h2));
            ll1.y = __float2bfloat16(v.w - __bfloat162float(h3));
            *(__nv_bfloat162*)&Bl[r][gcol]     = ll0;
            *(__nv_bfloat162*)&Bl[r][gcol + 2] = ll1;
        }
        __syncthreads();

        #pragma unroll
        for (int kk = 0; kk < 2; kk++) {
            const int k16 = kk * 16;
            uint32_t ah[2][4], al[2][4], bh[2][4], bl[2][4];
            #pragma unroll
            for (int mi = 0; mi < 2; mi++) {
                ldsm4(ah[mi], s2u(&Ah[wm + mi * 16 + lr][k16 + lc]));
                ldsm4(al[mi], s2u(&Al[wm + mi * 16 + lr][k16 + lc]));
            }
            #pragma unroll
            for (int nj = 0; nj < 2; nj++) {
                ldsm4(bh[nj], s2u(&Bh[wn + nj * 16 + lr][k16 + lc]));
                ldsm4(bl[nj], s2u(&Bl[wn + nj * 16 + lr][k16 + lc]));
            }
            #pragma unroll
            for (int mi = 0; mi < 2; mi++)
                #pragma unroll
                for (int nf = 0; nf < 4; nf++) {
                    int nj = nf >> 1, sub = nf & 1;
                    mma16816(acc[mi][nf], ah[mi], bh[nj][sub], bh[nj][sub + 2]);
                    mma16816(acc[mi][nf], ah[mi], bl[nj][sub], bl[nj][sub + 2]);
                    mma16816(acc[mi][nf], al[mi], bh[nj][sub], bh[nj][sub + 2]);
                }
        }
        __syncthreads();
    }

    #pragma unroll
    for (int mi = 0; mi < 2; mi++)
        #pragma unroll
        for (int nf = 0; nf < 4; nf++) {
            int row = m0 + wm + mi * 16 + (lane >> 2);
            int col = n0 + wn + nf * 8 + ((lane & 3) << 1);
            float2 v0; v0.x = acc[mi][nf][0]; v0.y = acc[mi][nf][1];
            float2 v1; v1.x = acc[mi][nf][2]; v1.y = acc[mi][nf][3];
            *(float2*)&C[(size_t)row * N + col]       = v0;
            *(float2*)&C[(size_t)(row + 8) * N + col] = v1;
        }
}

// ---------------- K3: causal depthwise conv (width 4) + SiLU ----------------
__global__ void conv_kernel(const float* __restrict__ cw,
                            const float* __restrict__ cb) {
    int d = blockIdx.y;
    int n = blockIdx.x * 256 + threadIdx.x;
    const float* xin = g_xz + (size_t)d * NT;
    float w0 = cw[d * 4 + 0], w1 = cw[d * 4 + 1];
    float w2 = cw[d * 4 + 2], w3 = cw[d * 4 + 3];
    int l = n & (LSEQ - 1);
    float v = cb[d] + w3 * xin[n];
    if (l >= 1) v = fmaf(w2, xin[n - 1], v);
    if (l >= 2) v = fmaf(w1, xin[n - 2], v);
    if (l >= 3) v = fmaf(w0, xin[n - 3], v);
    v = v / (1.f + __expf(-v));          // SiLU
    g_xc[(size_t)d * NT + n] = v;
}

// ---------------- K4: x_proj (48x512) @ xc -> dt/Bm/Cm in (n,16) layout -----
__global__ void xproj_kernel(const float* __restrict__ W) {
    __shared__ float Ws[48][64];
    __shared__ float Xs[64][68];
    int t  = threadIdx.x;
    int n0 = blockIdx.x * 64;
    int tn = t & 63, tk = t >> 6;        // tk 0..3, each owns 12 k-rows
    float acc[12];
    #pragma unroll
    for (int j = 0; j < 12; j++) acc[j] = 0.f;

    for (int d0 = 0; d0 < DIN; d0 += 64) {
        __syncthreads();
        for (int i = t; i < 768; i += 256) {           // W chunk 48x64
            int r = i >> 4, c4 = (i & 15) << 2;
            *(float4*)&Ws[r][c4] = *(const float4*)&W[(size_t)r * DIN + d0 + c4];
        }
        for (int i = t; i < 1024; i += 256) {          // X chunk 64x64
            int r = i >> 4, c4 = (i & 15) << 2;
            *(float4*)&Xs[r][c4] = *(const float4*)&g_xc[(size_t)(d0 + r) * NT + n0 + c4];
        }
        __syncthreads();
        #pragma unroll 4
        for (int dd = 0; dd < 64; dd++) {
            float xv = Xs[dd][tn];
            #pragma unroll
            for (int j = 0; j < 12; j++)
                acc[j] = fmaf(xv, Ws[tk * 12 + j][dd], acc[j]);
        }
    }
    int n = n0 + tn;
    #pragma unroll
    for (int j = 0; j < 12; j++) {
        int k = tk * 12 + j;
        if (k < DTRANK)                g_dt[(size_t)n * 16 + k] = acc[j];
        else if (k < DTRANK + DSTATE)  g_Bm[(size_t)n * 16 + (k - DTRANK)] = acc[j];
        else                           g_Cm[(size_t)n * 16 + (k - DTRANK - DSTATE)] = acc[j];
    }
}

// ---------------- K5: delta = softplus(dt @ dtw^T + dtb)  -> (DIN, NT) ------
__global__ void delta_kernel(const float* __restrict__ dtw,
                             const float* __restrict__ dtb) {
    int d = blockIdx.y;
    int n = blockIdx.x * 256 + threadIdx.x;
    float s = dtb[d];
    const float4* dtn = (const float4*)(g_dt + (size_t)n * 16);
    const float4* wr  = (const float4*)(dtw + d * 16);
    #pragma unroll
    for (int q = 0; q < 4; q++) {
        float4 a = dtn[q], b = wr[q];
        s += a.x * b.x + a.y * b.y + a.z * b.z + a.w * b.w;
    }
    float delta = (s > 20.f) ? s : log1pf(__expf(s));
    g_delta[(size_t)d * NT + n] = delta;
}

// ---------------- K6a: chunk scan pass1 — per-chunk (P, q) ------------------
// group of 16 lanes = one (b, chunk, d); P = prod dA, q = chunk-local state.
__global__ void scan_p1_kernel(const float* __restrict__ Alog) {
    int b  = blockIdx.z;
    int ch = blockIdx.y;
    int g  = threadIdx.x >> 4;
    int nl = threadIdx.x & 15;
    int d  = blockIdx.x * 16 + g;

    float Adn = -__expf(Alog[d * DSTATE + nl]);
    float P = 1.f, q = 0.f;
    int base = b * LSEQ + ch * CHLEN;
    const float* drow  = g_delta + (size_t)d * NT + base;
    const float* xcrow = g_xc    + (size_t)d * NT + base;
    const float* Bp    = g_Bm + (size_t)base * 16;

    #pragma unroll 4
    for (int l = 0; l < CHLEN; l++) {
        float delta = drow[l];
        float dA = __expf(delta * Adn);
        q = fmaf(dA, q, delta * Bp[l * 16 + nl] * xcrow[l]);
        P *= dA;
    }
    size_t idx = ((size_t)(b * NCHUNK + ch) * DIN + d) * 16 + nl;
    g_P[idx] = P;
    g_q[idx] = q;
}

// ---------------- K6b: prefix over chunks -> h0 per (b, chunk, d, n) --------
__global__ void scan_p2_kernel() {
    int idx = blockIdx.x * 256 + threadIdx.x;     // (b, d, n) flat: b*8192 + d*16 + n
    int n = idx & 15;
    int d = (idx >> 4) & (DIN - 1);
    int b = idx >> 13;
    float h = 0.f;
    #pragma unroll
    for (int ch = 0; ch < NCHUNK; ch++) {
        size_t p = ((size_t)(b * NCHUNK + ch) * DIN + d) * 16 + n;
        g_h0[p] = h;
        h = fmaf(g_P[p], h, g_q[p]);
    }
}

// ---------------- K6c: chunk scan pass3 — replay + y + gating ---------------
__global__ void scan_p3_kernel(const float* __restrict__ Alog,
                               const float* __restrict__ Dp) {
    int b  = blockIdx.z;
    int ch = blockIdx.y;
    int g  = threadIdx.x >> 4;
    int nl = threadIdx.x & 15;
    int d  = blockIdx.x * 16 + g;

    float Adn = -__expf(Alog[d * DSTATE + nl]);
    float Dd  = Dp[d];
    float h = g_h0[((size_t)(b * NCHUNK + ch) * DIN + d) * 16 + nl];

    int base = b * LSEQ + ch * CHLEN;
    const float* drow  = g_delta + (size_t)d * NT + base;
    const float* xcrow = g_xc    + (size_t)d * NT + base;
    const float* zrow  = g_xz + (size_t)(DIN + d) * NT + base;
    const float* Bp = g_Bm + (size_t)base * 16;
    const float* Cp = g_Cm + (size_t)base * 16;

    #pragma unroll 4
    for (int l = 0; l < CHLEN; l++) {
        float delta = drow[l];
        float xcv = xcrow[l];
        float dA = __expf(delta * Adn);
        h = fmaf(dA, h, delta * Bp[l * 16 + nl] * xcv);
        float yv = h * Cp[l * 16 + nl];
        yv += __shfl_xor_sync(0xffffffffu, yv, 1);
        yv += __shfl_xor_sync(0xffffffffu, yv, 2);
        yv += __shfl_xor_sync(0xffffffffu, yv, 4);
        yv += __shfl_xor_sync(0xffffffffu, yv, 8);
        if (nl == 0) {
            float zl = zrow[l];
            float silu = zl / (1.f + __expf(-zl));
            g_y[(size_t)(base + l) * DIN + d] = (yv + Dd * xcv) * silu;
        }
    }
}

// ---------------- K7: residual + output LayerNorm, write (B,C,L,1) ---------
__global__ void ln_out_kernel(const float* __restrict__ x,
                              const float* __restrict__ w,
                              const float* __restrict__ bias,
                              float* __restrict__ out) {
    int b  = blockIdx.y;
    int lx = threadIdx.x;
    int ty = threadIdx.y;
    int l  = blockIdx.x * 32 + lx;
    __shared__ float sS[8][32], sQ[8][32], sMean[32], sR[32];

    const float* xb = x + (size_t)b * CDIM * LSEQ + l;
    const float* ob = g_op + (size_t)b * LSEQ + l;
    float s = 0.f, q = 0.f;
    for (int c = ty; c < CDIM; c += 8) {
        float v = ob[(size_t)c * NT] + xb[(size_t)c * LSEQ];
        s += v; q += v * v;
    }
    sS[ty][lx] = s; sQ[ty][lx] = q;
    __syncthreads();
    if (ty == 0) {
        float ts = 0.f, tq = 0.f;
        #pragma unroll
        for (int i = 0; i < 8; i++) { ts += sS[i][lx]; tq += sQ[i][lx]; }
        float m   = ts * (1.f / CDIM);
        float var = tq * (1.f / CDIM) - m * m;
        sMean[lx] = m;
        sR[lx]    = rsqrtf(var + 1e-5f);
    }
    __syncthreads();
    float m = sMean[lx], r = sR[lx];
    float* outb = out + (size_t)b * CDIM * LSEQ + l;
    for (int c = ty; c < CDIM; c += 8) {
        float v = ob[(size_t)c * NT] + xb[(size_t)c * LSEQ];
        outb[(size_t)c * LSEQ] = (v - m) * r * w[c] + bias[c];
    }
}

// ---------------- launch -----------------------------------------------------
extern "C" void kernel_launch(void* const* d_in, const int* in_sizes, int n_in,
                              void* d_out, int out_size) {
    const float* x         = (const float*)d_in[0];
    const float* ln_w      = (const float*)d_in[1];
    const float* ln_b      = (const float*)d_in[2];
    const float* in_proj_w = (const float*)d_in[3];
    const float* conv_w    = (const float*)d_in[4];
    const float* conv_b    = (const float*)d_in[5];
    const float* x_proj_w  = (const float*)d_in[6];
    const float* dt_proj_w = (const float*)d_in[7];
    const float* dt_proj_b = (const float*)d_in[8];
    const float* A_log     = (const float*)d_in[9];
    const float* Dv        = (const float*)d_in[10];
    const float* out_proj_w= (const float*)d_in[11];
    float* out = (float*)d_out;

    float *p_u, *p_xz, *p_y, *p_op;
    cudaGetSymbolAddress((void**)&p_u,  g_u);
    cudaGetSymbolAddress((void**)&p_xz, g_xz);
    cudaGetSymbolAddress((void**)&p_y,  g_y);
    cudaGetSymbolAddress((void**)&p_op, g_op);

    ln_in_kernel<<<dim3(LSEQ / 32, BATCH), 256>>>(x, ln_w, ln_b);

    // in_proj: (1024 x 256) @ (8192 x 256)^T -> (1024, 8192)
    gemm_tc_kernel<<<dim3(NT / 64, (2 * DIN) / 128), 256>>>(
        in_proj_w, p_u, p_xz, 2 * DIN, NT, CDIM);

    conv_kernel<<<dim3(NT / 256, DIN), 256>>>(conv_w, conv_b);

    xproj_kernel<<<dim3(NT / 64), 256>>>(x_proj_w);

    delta_kernel<<<dim3(NT / 256, DIN), 256>>>(dt_proj_w, dt_proj_b);

    scan_p1_kernel<<<dim3(DIN / 16, NCHUNK, BATCH), 256>>>(A_log);
    scan_p2_kernel<<<dim3(BATCH * DIN * 16 / 256), 256>>>();
    scan_p3_kernel<<<dim3(DIN / 16, NCHUNK, BATCH), 256>>>(A_log, Dv);

    // out_proj: (256 x 512) @ (8192 x 512)^T -> (256, 8192)
    gemm_tc_kernel<<<dim3(NT / 64, CDIM / 128), 256>>>(
        out_proj_w, p_y, p_op, CDIM, NT, DIN);

    ln_out_kernel<<<dim3(LSEQ / 32, BATCH), dim3(32, 8)>>>(x, ln_w, ln_b, out);
}